// round 3
// baseline (speedup 1.0000x reference)
#include <cuda_runtime.h>
#include <cuda_bf16.h>
#include <mma.h>
#include <math.h>

using namespace nvcuda;

#define NA 50000
#define NE 800000
#define ND 64
#define FULL 192
#define NOUT 128          // combined: cols 0..63 = core, 64..127 = filter
#define ET 64             // edges per block
#define ZLD 132           // fp32 z-tile leading dim (528B rows, 16B-multiple)
#define CLD 136           // fp32 C-tile leading dim (544B rows, 16B-multiple)
#define BN_EPS 1e-5f

// Wt[k][o] = W[o][k] as tf32-rounded fp32 (bias cancels inside batchnorm)
__device__ float g_Wt[FULL * NOUT];
__device__ float g_sum[NOUT];
__device__ float g_sumsq[NOUT];
__device__ float g_scale[NOUT];   // invstd * gamma
__device__ float g_shift[NOUT];   // beta - mean * invstd * gamma
__device__ int   g_idx64;         // 1 if edge_indices is int64, 0 if int32

// ---------------------------------------------------------------------------
// prep: out = atom_features copy, W -> transposed tf32, zero stats,
//       detect edge_indices dtype (int64 vs int32)
// ---------------------------------------------------------------------------
__global__ void prep_kernel(const float* __restrict__ atom,
                            const float* __restrict__ Wf,
                            const float* __restrict__ Wc,
                            const int* __restrict__ eidx_i32,
                            float* __restrict__ out) {
    int tid = blockIdx.x * blockDim.x + threadIdx.x;
    int stride = gridDim.x * blockDim.x;
    for (int i = tid; i < NA * ND; i += stride) out[i] = atom[i];
    for (int i = tid; i < FULL * NOUT; i += stride) {
        int k = i / NOUT, o = i % NOUT;
        float w = (o < ND) ? Wc[o * FULL + k] : Wf[(o - ND) * FULL + k];
        g_Wt[i] = wmma::__float_to_tf32(w);
    }
    if (tid < NOUT) { g_sum[tid] = 0.f; g_sumsq[tid] = 0.f; }
    if (tid == 0) {
        // int64 layout => odd int32 words are zero high-words.
        int any = 0;
        for (int k = 0; k < 512; k++) any |= eidx_i32[2 * k + 1];
        g_idx64 = (any == 0) ? 1 : 0;
    }
}

// ---------------------------------------------------------------------------
// finalize: fold batchnorm into per-column scale/shift
// ---------------------------------------------------------------------------
__global__ void finalize_kernel(const float* __restrict__ gc,
                                const float* __restrict__ bc,
                                const float* __restrict__ gf,
                                const float* __restrict__ bf) {
    int c = threadIdx.x;
    if (c < NOUT) {
        float mean = g_sum[c] * (1.f / (float)NE);
        float var  = g_sumsq[c] * (1.f / (float)NE) - mean * mean;
        float inv  = rsqrtf(var + BN_EPS);
        float gamma = (c < ND) ? gc[c] : gf[c - ND];
        float beta  = (c < ND) ? bc[c] : bf[c - ND];
        g_scale[c] = inv * gamma;
        g_shift[c] = beta - mean * inv * gamma;
    }
}

// ---------------------------------------------------------------------------
// GEMM over 64 edges/block, 128 output cols, K=192 tf32 wmma, fp32 accum.
// K is split: phase A = atom[dst]|atom[src] (128 cols), phase B = edge (64).
// PHASE 0: accumulate per-column sum / sumsq.
// PHASE 1: apply folded BN, softplus*sigmoid, red.v4 scatter to out[dst].
// ---------------------------------------------------------------------------
template <int PHASE>
__global__ __launch_bounds__(256)
void gemm_kernel(const float* __restrict__ atom,
                 const float* __restrict__ edgef,
                 const void*  __restrict__ eidx,
                 float* __restrict__ out) {
    // union: z tile (64x132 f32 = 33792B) / C tile (64x136 f32 = 34816B)
    __shared__ __align__(16) char smem_raw[ET * CLD * 4];
    __shared__ int   sSrc[ET];
    __shared__ int   sDst[ET];
    __shared__ float sBN[2 * NOUT];
    float* zs = reinterpret_cast<float*>(smem_raw);
    float* Cs = reinterpret_cast<float*>(smem_raw);

    const int tid = threadIdx.x;
    const int e0  = blockIdx.x * ET;

    // ---- stage edge indices (dtype detected at runtime) ----
    if (tid < ET) {
        int e = e0 + tid;
        if (g_idx64) {
            const long long* p = reinterpret_cast<const long long*>(eidx);
            sSrc[tid] = (int)p[2ll * e];
            sDst[tid] = (int)p[2ll * e + 1];
        } else {
            const int* p = reinterpret_cast<const int*>(eidx);
            sSrc[tid] = p[2 * e];
            sDst[tid] = p[2 * e + 1];
        }
    }
    if (PHASE == 1 && tid >= 128 && tid < 128 + NOUT) {
        int c = tid - 128;
        sBN[c]        = g_scale[c];
        sBN[NOUT + c] = g_shift[c];
    }
    __syncthreads();

    const int w  = tid >> 5;
    const int mt = w & 3;          // m-tile: 16 edges
    const int ng = w >> 2;         // n-group: 4 tiles of 16 cols

    wmma::fragment<wmma::matrix_a, 16, 16, 8, wmma::precision::tf32, wmma::row_major> a;
    wmma::fragment<wmma::matrix_b, 16, 16, 8, wmma::precision::tf32, wmma::row_major> b;
    wmma::fragment<wmma::accumulator, 16, 16, 8, float> acc[4];
#pragma unroll
    for (int j = 0; j < 4; j++) wmma::fill_fragment(acc[j], 0.f);

    // ---- phase A gather: z[:,0:128] = [atom[dst] | atom[src]] (tf32) ----
    for (int i = tid; i < ET * 32; i += 256) {
        int e = i / 32, seg = i % 32;
        int col = seg * 4;
        const float* p = (seg < 16) ? atom + (long long)sDst[e] * ND + col
                                    : atom + (long long)sSrc[e] * ND + (col - 64);
        float4 v = *reinterpret_cast<const float4*>(p);
        float* zp = zs + e * ZLD + col;
        zp[0] = wmma::__float_to_tf32(v.x);
        zp[1] = wmma::__float_to_tf32(v.y);
        zp[2] = wmma::__float_to_tf32(v.z);
        zp[3] = wmma::__float_to_tf32(v.w);
    }
    __syncthreads();

    // ---- phase A mma: W rows 0..127 ----
#pragma unroll
    for (int k = 0; k < 16; k++) {
        wmma::load_matrix_sync(a, zs + (mt * 16) * ZLD + k * 8, ZLD);
#pragma unroll
        for (int j = 0; j < 4; j++) {
            wmma::load_matrix_sync(b, g_Wt + (k * 8) * NOUT + (ng * 4 + j) * 16, NOUT);
            wmma::mma_sync(acc[j], a, b, acc[j]);
        }
    }
    __syncthreads();

    // ---- phase B gather: z[:,0:64] = edge_features (tf32) ----
    for (int i = tid; i < ET * 16; i += 256) {
        int e = i / 16, q = i % 16;
        int col = q * 4;
        float4 v = *reinterpret_cast<const float4*>(
            edgef + (long long)(e0 + e) * ND + col);
        float* zp = zs + e * ZLD + col;
        zp[0] = wmma::__float_to_tf32(v.x);
        zp[1] = wmma::__float_to_tf32(v.y);
        zp[2] = wmma::__float_to_tf32(v.z);
        zp[3] = wmma::__float_to_tf32(v.w);
    }
    __syncthreads();

    // ---- phase B mma: W rows 128..191 ----
#pragma unroll
    for (int k = 0; k < 8; k++) {
        wmma::load_matrix_sync(a, zs + (mt * 16) * ZLD + k * 8, ZLD);
#pragma unroll
        for (int j = 0; j < 4; j++) {
            wmma::load_matrix_sync(b, g_Wt + (128 + k * 8) * NOUT + (ng * 4 + j) * 16, NOUT);
            wmma::mma_sync(acc[j], a, b, acc[j]);
        }
    }
    __syncthreads();   // all warps done reading zs before C overwrites it

#pragma unroll
    for (int j = 0; j < 4; j++)
        wmma::store_matrix_sync(Cs + (mt * 16) * CLD + (ng * 4 + j) * 16,
                                acc[j], CLD, wmma::mem_row_major);
    __syncthreads();

    if (PHASE == 0) {
        // column reduce over the 64 edges of this block
        if (tid < NOUT) {
            float s = 0.f, sq = 0.f;
#pragma unroll 4
            for (int e = 0; e < ET; e++) {
                float v = Cs[e * CLD + tid];
                s += v; sq += v * v;
            }
            atomicAdd(&g_sum[tid], s);
            atomicAdd(&g_sumsq[tid], sq);
        }
    } else {
        // message + scatter: 64 edges x 16 float4-quads = 1024 tasks / 256 thr
        for (int i = tid; i < ET * 16; i += 256) {
            int e = i >> 4, q = i & 15;
            float m[4];
#pragma unroll
            for (int u = 0; u < 4; u++) {
                int c = q * 4 + u;
                float xc = Cs[e * CLD + c]      * sBN[c]      + sBN[NOUT + c];
                float xf = Cs[e * CLD + 64 + c] * sBN[64 + c] + sBN[NOUT + 64 + c];
                // softplus(core) * sigmoid(filter)
                float sp = fmaxf(xc, 0.f) + log1pf(expf(-fabsf(xc)));
                float sg = 1.f / (1.f + expf(-xf));
                m[u] = sp * sg;
            }
            float* ptr = out + (long long)sDst[e] * ND + q * 4;
            asm volatile("red.global.add.v4.f32 [%0], {%1,%2,%3,%4};"
                         :: "l"(ptr), "f"(m[0]), "f"(m[1]), "f"(m[2]), "f"(m[3])
                         : "memory");
        }
    }
}

// ---------------------------------------------------------------------------
extern "C" void kernel_launch(void* const* d_in, const int* in_sizes, int n_in,
                              void* d_out, int out_size) {
    const float* atom  = (const float*)d_in[0];
    const float* edgef = (const float*)d_in[1];
    const float* Wf    = (const float*)d_in[2];
    const float* gf    = (const float*)d_in[4];
    const float* bf    = (const float*)d_in[5];
    const float* Wc    = (const float*)d_in[6];
    const float* gc    = (const float*)d_in[8];
    const float* bc    = (const float*)d_in[9];
    const void*  eidx  = d_in[10];
    float* out = (float*)d_out;

    prep_kernel<<<2048, 256>>>(atom, Wf, Wc, (const int*)eidx, out);
    gemm_kernel<0><<<NE / ET, 256>>>(atom, edgef, eidx, out);
    finalize_kernel<<<1, 128>>>(gc, bc, gf, bf);
    gemm_kernel<1><<<NE / ET, 256>>>(atom, edgef, eidx, out);
}

// round 4
// speedup vs baseline: 1.7138x; 1.7138x over previous
#include <cuda_runtime.h>
#include <cuda_bf16.h>
#include <mma.h>
#include <math.h>

using namespace nvcuda;

#define NA 50000
#define NE 800000
#define ND 64
#define FULL 192
#define NOUT 128          // combined: cols 0..63 = core, 64..127 = filter
#define ET 128            // edges per block (pass 0)
#define ZLD 68            // fp32 z-tile leading dim (272B rows, 16B-multiple)
#define BN_EPS 1e-5f

// Wt[k][o] = W[o][k] as tf32-rounded fp32 (bias cancels inside batchnorm)
__device__ float g_Wt[FULL * NOUT];
__device__ float g_sum[NOUT];
__device__ float g_sumsq[NOUT];
__device__ float g_scale[NOUT];   // invstd * gamma
__device__ float g_shift[NOUT];   // beta - mean * invstd * gamma
__device__ int   g_idx64;         // 1 if edge_indices is int64, 0 if int32
// pre-activation scratch: 800k x 128 fp32 = 409.6 MB
__device__ float g_pre[(size_t)NE * NOUT];

// ---------------------------------------------------------------------------
// prep: out = atom_features copy, W -> transposed tf32, zero stats,
//       detect edge_indices dtype (int64 vs int32)
// ---------------------------------------------------------------------------
__global__ void prep_kernel(const float* __restrict__ atom,
                            const float* __restrict__ Wf,
                            const float* __restrict__ Wc,
                            const int* __restrict__ eidx_i32,
                            float* __restrict__ out) {
    int tid = blockIdx.x * blockDim.x + threadIdx.x;
    int stride = gridDim.x * blockDim.x;
    for (int i = tid; i < NA * ND; i += stride) out[i] = atom[i];
    for (int i = tid; i < FULL * NOUT; i += stride) {
        int k = i / NOUT, o = i % NOUT;
        float w = (o < ND) ? Wc[o * FULL + k] : Wf[(o - ND) * FULL + k];
        g_Wt[i] = wmma::__float_to_tf32(w);
    }
    if (tid < NOUT) { g_sum[tid] = 0.f; g_sumsq[tid] = 0.f; }
    if (tid == 0) {
        // int64 layout => odd int32 words are zero high-words.
        int any = 0;
        for (int k = 0; k < 512; k++) any |= eidx_i32[2 * k + 1];
        g_idx64 = (any == 0) ? 1 : 0;
    }
}

// ---------------------------------------------------------------------------
// finalize: fold batchnorm into per-column scale/shift
// ---------------------------------------------------------------------------
__global__ void finalize_kernel(const float* __restrict__ gc,
                                const float* __restrict__ bc,
                                const float* __restrict__ gf,
                                const float* __restrict__ bf) {
    int c = threadIdx.x;
    if (c < NOUT) {
        float mean = g_sum[c] * (1.f / (float)NE);
        float var  = g_sumsq[c] * (1.f / (float)NE) - mean * mean;
        float inv  = rsqrtf(var + BN_EPS);
        float gamma = (c < ND) ? gc[c] : gf[c - ND];
        float beta  = (c < ND) ? bc[c] : bf[c - ND];
        g_scale[c] = inv * gamma;
        g_shift[c] = beta - mean * inv * gamma;
    }
}

// ---------------------------------------------------------------------------
// PASS 0: tf32 GEMM over 128 edges/block. K split into 3 phases of 64 cols
// (atom[dst] | atom[src] | edge_feat) so the z-tile stays at 34 KB static
// smem. Accumulators stream straight to g_pre (global); per-block column
// stats re-read from L2 and atomically folded into g_sum/g_sumsq.
// ---------------------------------------------------------------------------
__global__ __launch_bounds__(256)
void pass0_kernel(const float* __restrict__ atom,
                  const float* __restrict__ edgef,
                  const void*  __restrict__ eidx) {
    __shared__ __align__(16) float zs[ET * ZLD];   // 34816 B
    __shared__ int sSrc[ET];
    __shared__ int sDst[ET];

    const int tid = threadIdx.x;
    const int e0  = blockIdx.x * ET;

    if (tid < ET) {
        int e = e0 + tid;
        if (g_idx64) {
            const long long* p = reinterpret_cast<const long long*>(eidx);
            sSrc[tid] = (int)p[2ll * e];
            sDst[tid] = (int)p[2ll * e + 1];
        } else {
            const int* p = reinterpret_cast<const int*>(eidx);
            sSrc[tid] = p[2 * e];
            sDst[tid] = p[2 * e + 1];
        }
    }
    __syncthreads();

    const int w  = tid >> 5;
    const int mg = w & 3;          // edge group: 32 edges (2 m-fragments)
    const int ng = w >> 2;         // col group: 64 cols (4 n-fragments)

    wmma::fragment<wmma::matrix_a, 16, 16, 8, wmma::precision::tf32, wmma::row_major> a0, a1;
    wmma::fragment<wmma::matrix_b, 16, 16, 8, wmma::precision::tf32, wmma::row_major> b;
    wmma::fragment<wmma::accumulator, 16, 16, 8, float> acc[2][4];
#pragma unroll
    for (int m = 0; m < 2; m++)
#pragma unroll
        for (int j = 0; j < 4; j++) wmma::fill_fragment(acc[m][j], 0.f);

#pragma unroll
    for (int p = 0; p < 3; p++) {
        // gather 64 cols for this phase
        for (int i = tid; i < ET * 16; i += 256) {
            int e = i >> 4, q = i & 15;
            int col = q * 4;
            const float* ptr;
            if (p == 0)      ptr = atom  + (long long)sDst[e] * ND + col;
            else if (p == 1) ptr = atom  + (long long)sSrc[e] * ND + col;
            else             ptr = edgef + (long long)(e0 + e) * ND + col;
            float4 v = *reinterpret_cast<const float4*>(ptr);
            float* zp = zs + e * ZLD + col;
            zp[0] = wmma::__float_to_tf32(v.x);
            zp[1] = wmma::__float_to_tf32(v.y);
            zp[2] = wmma::__float_to_tf32(v.z);
            zp[3] = wmma::__float_to_tf32(v.w);
        }
        __syncthreads();

#pragma unroll
        for (int k = 0; k < 8; k++) {
            wmma::load_matrix_sync(a0, zs + (mg * 32)      * ZLD + k * 8, ZLD);
            wmma::load_matrix_sync(a1, zs + (mg * 32 + 16) * ZLD + k * 8, ZLD);
#pragma unroll
            for (int j = 0; j < 4; j++) {
                wmma::load_matrix_sync(
                    b, g_Wt + (p * 64 + k * 8) * NOUT + (ng * 64 + j * 16), NOUT);
                wmma::mma_sync(acc[0][j], a0, b, acc[0][j]);
                wmma::mma_sync(acc[1][j], a1, b, acc[1][j]);
            }
        }
        __syncthreads();   // before next gather overwrites zs
    }

    // stream accumulators to global scratch
#pragma unroll
    for (int m = 0; m < 2; m++)
#pragma unroll
        for (int j = 0; j < 4; j++)
            wmma::store_matrix_sync(
                g_pre + (size_t)(e0 + mg * 32 + m * 16) * NOUT + ng * 64 + j * 16,
                acc[m][j], NOUT, wmma::mem_row_major);
    __syncthreads();

    // per-block column stats from just-written rows (L2 hits, coalesced)
    if (tid < NOUT) {
        const float* base = g_pre + (size_t)e0 * NOUT + tid;
        float s = 0.f, sq = 0.f;
#pragma unroll 4
        for (int e = 0; e < ET; e++) {
            float v = base[(size_t)e * NOUT];
            s += v; sq += v * v;
        }
        atomicAdd(&g_sum[tid], s);
        atomicAdd(&g_sumsq[tid], sq);
    }
}

// ---------------------------------------------------------------------------
// PASS 1: streaming epilogue. One thread per (edge, quad-of-4-cols):
// read pre-act, folded BN, softplus*sigmoid, red.v4 scatter to out[dst].
// ---------------------------------------------------------------------------
__global__ __launch_bounds__(256)
void pass1_kernel(const void* __restrict__ eidx,
                  float* __restrict__ out) {
    __shared__ float sBN[2 * NOUT];
    const int tid = threadIdx.x;
    if (tid < NOUT)        sBN[tid]       = g_scale[tid];
    else                   sBN[128 + (tid - 128)] = g_shift[tid - 128];
    __syncthreads();

    long long i = (long long)blockIdx.x * 256 + tid;   // NE*16 = 12.8M exact
    int e = (int)(i >> 4), q = (int)(i & 15);

    int dst;
    if (g_idx64) dst = (int)reinterpret_cast<const long long*>(eidx)[2ll * e + 1];
    else         dst = reinterpret_cast<const int*>(eidx)[2 * e + 1];

    const float* row = g_pre + (size_t)e * NOUT;
    float4 xc4 = *reinterpret_cast<const float4*>(row + q * 4);
    float4 xf4 = *reinterpret_cast<const float4*>(row + 64 + q * 4);
    float xc[4] = {xc4.x, xc4.y, xc4.z, xc4.w};
    float xf[4] = {xf4.x, xf4.y, xf4.z, xf4.w};

    float m[4];
#pragma unroll
    for (int u = 0; u < 4; u++) {
        int c = q * 4 + u;
        float vc = xc[u] * sBN[c]      + sBN[NOUT + c];
        float vf = xf[u] * sBN[64 + c] + sBN[NOUT + 64 + c];
        float sp = fmaxf(vc, 0.f) + log1pf(expf(-fabsf(vc)));   // softplus
        float sg = 1.f / (1.f + expf(-vf));                     // sigmoid
        m[u] = sp * sg;
    }
    float* ptr = out + (long long)dst * ND + q * 4;
    asm volatile("red.global.add.v4.f32 [%0], {%1,%2,%3,%4};"
                 :: "l"(ptr), "f"(m[0]), "f"(m[1]), "f"(m[2]), "f"(m[3])
                 : "memory");
}

// ---------------------------------------------------------------------------
extern "C" void kernel_launch(void* const* d_in, const int* in_sizes, int n_in,
                              void* d_out, int out_size) {
    const float* atom  = (const float*)d_in[0];
    const float* edgef = (const float*)d_in[1];
    const float* Wf    = (const float*)d_in[2];
    const float* gf    = (const float*)d_in[4];
    const float* bf    = (const float*)d_in[5];
    const float* Wc    = (const float*)d_in[6];
    const float* gc    = (const float*)d_in[8];
    const float* bc    = (const float*)d_in[9];
    const void*  eidx  = d_in[10];
    float* out = (float*)d_out;

    prep_kernel<<<2048, 256>>>(atom, Wf, Wc, (const int*)eidx, out);
    pass0_kernel<<<NE / ET, 256>>>(atom, edgef, eidx);
    finalize_kernel<<<1, 128>>>(gc, bc, gf, bf);
    pass1_kernel<<<(NE * 16) / 256, 256>>>(eidx, out);
}

// round 5
// speedup vs baseline: 1.7251x; 1.0066x over previous
#include <cuda_runtime.h>
#include <cuda_bf16.h>
#include <mma.h>
#include <math.h>

using namespace nvcuda;

#define NA 50000
#define NE 800000
#define ND 64
#define FULL 192
#define NOUT 128          // combined: cols 0..63 = core, 64..127 = filter
#define ET 128            // edges per block (pass 0)
#define ZLD 196           // fp32 z-tile leading dim (784B rows, 16B-multiple)
#define THREADS0 512
#define BN_EPS 1e-5f

// dynamic smem: W (192x128 f32) + z (128x196 f32) + src/dst idx
#define SMEM0_BYTES ((FULL * NOUT + ET * ZLD) * 4 + 2 * ET * 4)

// Wt[k][o] = W[o][k] as tf32-rounded fp32 (bias cancels inside batchnorm)
__device__ __align__(16) float g_Wt[FULL * NOUT];
__device__ float g_sum[NOUT];
__device__ float g_sumsq[NOUT];
__device__ float g_scale[NOUT];   // invstd * gamma
__device__ float g_shift[NOUT];   // beta - mean * invstd * gamma
__device__ int   g_idx64;         // 1 if edge_indices is int64, 0 if int32
// pre-activation scratch: 800k x 128 fp32 = 409.6 MB
__device__ float g_pre[(size_t)NE * NOUT];

__device__ __forceinline__ void cp_async16(void* sdst, const void* gsrc) {
    unsigned saddr = (unsigned)__cvta_generic_to_shared(sdst);
    asm volatile("cp.async.ca.shared.global [%0], [%1], 16;"
                 :: "r"(saddr), "l"(gsrc) : "memory");
}

// ---------------------------------------------------------------------------
// prep: out = atom copy, W -> transposed tf32, zero stats, idx dtype sniff
// ---------------------------------------------------------------------------
__global__ void prep_kernel(const float* __restrict__ atom,
                            const float* __restrict__ Wf,
                            const float* __restrict__ Wc,
                            const int* __restrict__ eidx_i32,
                            float* __restrict__ out) {
    int tid = blockIdx.x * blockDim.x + threadIdx.x;
    int stride = gridDim.x * blockDim.x;
    for (int i = tid; i < NA * ND; i += stride) out[i] = atom[i];
    for (int i = tid; i < FULL * NOUT; i += stride) {
        int k = i / NOUT, o = i % NOUT;
        float w = (o < ND) ? Wc[o * FULL + k] : Wf[(o - ND) * FULL + k];
        g_Wt[i] = wmma::__float_to_tf32(w);
    }
    if (tid < NOUT) { g_sum[tid] = 0.f; g_sumsq[tid] = 0.f; }
    if (tid == 0) {
        // int64 layout => odd int32 words are zero high-words.
        int any = 0;
        for (int k = 0; k < 512; k++) any |= eidx_i32[2 * k + 1];
        g_idx64 = (any == 0) ? 1 : 0;
    }
}

// ---------------------------------------------------------------------------
// finalize: fold batchnorm into per-column scale/shift
// ---------------------------------------------------------------------------
__global__ void finalize_kernel(const float* __restrict__ gc,
                                const float* __restrict__ bc,
                                const float* __restrict__ gf,
                                const float* __restrict__ bf) {
    int c = threadIdx.x;
    if (c < NOUT) {
        float mean = g_sum[c] * (1.f / (float)NE);
        float var  = g_sumsq[c] * (1.f / (float)NE) - mean * mean;
        float inv  = rsqrtf(var + BN_EPS);
        float gamma = (c < ND) ? gc[c] : gf[c - ND];
        float beta  = (c < ND) ? bc[c] : bf[c - ND];
        g_scale[c] = inv * gamma;
        g_shift[c] = beta - mean * inv * gamma;
    }
}

// ---------------------------------------------------------------------------
// PASS 0: tf32 GEMM, 128 edges/block, 512 threads (16 warps = 4m x 4n).
// W resident in smem; z gathered full-width via cp.async (HW tf32-truncates).
// Accumulators stream to g_pre; per-block column stats -> g_sum/g_sumsq.
// ---------------------------------------------------------------------------
__global__ __launch_bounds__(THREADS0)
void pass0_kernel(const float* __restrict__ atom,
                  const float* __restrict__ edgef,
                  const void*  __restrict__ eidx) {
    extern __shared__ __align__(16) float smem[];
    float* sW = smem;                    // 192*128 = 24576 floats (96 KB)
    float* zs = smem + FULL * NOUT;      // 128*196 = 25088 floats (98 KB)
    int*  sSrc = (int*)(zs + ET * ZLD);
    int*  sDst = sSrc + ET;

    const int tid = threadIdx.x;
    const int e0  = blockIdx.x * ET;

    // W: global(L2) -> smem, 16B chunks
    for (int i = tid; i < (FULL * NOUT) / 4; i += THREADS0)
        cp_async16(sW + i * 4, g_Wt + i * 4);

    // stage indices
    if (tid < ET) {
        int e = e0 + tid;
        if (g_idx64) {
            const long long* p = reinterpret_cast<const long long*>(eidx);
            sSrc[tid] = (int)p[2ll * e];
            sDst[tid] = (int)p[2ll * e + 1];
        } else {
            const int* p = reinterpret_cast<const int*>(eidx);
            sSrc[tid] = p[2 * e];
            sDst[tid] = p[2 * e + 1];
        }
    }
    __syncthreads();   // indices visible

    // gather z = [atom[dst] | atom[src] | edge_feat], 48 float4 per edge
    for (int i = tid; i < ET * 48; i += THREADS0) {
        int e = i / 48, seg = i % 48;
        int col = seg * 4;
        const float* g;
        if (seg < 16)      g = atom  + (long long)sDst[e] * ND + col;
        else if (seg < 32) g = atom  + (long long)sSrc[e] * ND + (col - 64);
        else               g = edgef + (long long)(e0 + e) * ND + (col - 128);
        cp_async16(zs + e * ZLD + col, g);
    }
    asm volatile("cp.async.commit_group;\ncp.async.wait_group 0;" ::: "memory");
    __syncthreads();

    // 16 warps: mg = warp&3 (2 m-frags = 32 edges), ng = warp>>2 (2 n-frags)
    const int w  = tid >> 5;
    const int m0 = (w & 3) * 32;
    const int n0 = (w >> 2) * 32;

    wmma::fragment<wmma::matrix_a, 16, 16, 8, wmma::precision::tf32, wmma::row_major> a0, a1;
    wmma::fragment<wmma::matrix_b, 16, 16, 8, wmma::precision::tf32, wmma::row_major> b0, b1;
    wmma::fragment<wmma::accumulator, 16, 16, 8, float> acc[2][2];
#pragma unroll
    for (int m = 0; m < 2; m++)
#pragma unroll
        for (int n = 0; n < 2; n++) wmma::fill_fragment(acc[m][n], 0.f);

#pragma unroll
    for (int k = 0; k < FULL / 8; k++) {
        wmma::load_matrix_sync(a0, zs + m0 * ZLD + k * 8, ZLD);
        wmma::load_matrix_sync(a1, zs + (m0 + 16) * ZLD + k * 8, ZLD);
        wmma::load_matrix_sync(b0, sW + (k * 8) * NOUT + n0, NOUT);
        wmma::load_matrix_sync(b1, sW + (k * 8) * NOUT + n0 + 16, NOUT);
        wmma::mma_sync(acc[0][0], a0, b0, acc[0][0]);
        wmma::mma_sync(acc[0][1], a0, b1, acc[0][1]);
        wmma::mma_sync(acc[1][0], a1, b0, acc[1][0]);
        wmma::mma_sync(acc[1][1], a1, b1, acc[1][1]);
    }

    // stream accumulators to global scratch
#pragma unroll
    for (int m = 0; m < 2; m++)
#pragma unroll
        for (int n = 0; n < 2; n++)
            wmma::store_matrix_sync(
                g_pre + (size_t)(e0 + m0 + m * 16) * NOUT + n0 + n * 16,
                acc[m][n], NOUT, wmma::mem_row_major);
    __syncthreads();   // all g_pre writes for this block visible

    // per-block column stats (rows just written, L2-resident)
    if (tid < NOUT) {
        const float* base = g_pre + (size_t)e0 * NOUT + tid;
        float s = 0.f, sq = 0.f;
#pragma unroll 4
        for (int e = 0; e < ET; e++) {
            float v = base[(size_t)e * NOUT];
            s += v; sq += v * v;
        }
        atomicAdd(&g_sum[tid], s);
        atomicAdd(&g_sumsq[tid], sq);
    }
}

// ---------------------------------------------------------------------------
// PASS 1: streaming epilogue. One thread per (edge, quad-of-4-cols):
// read pre-act, folded BN, softplus*sigmoid, red.v4 scatter to out[dst].
// ---------------------------------------------------------------------------
__global__ __launch_bounds__(256)
void pass1_kernel(const void* __restrict__ eidx,
                  float* __restrict__ out) {
    __shared__ float sBN[2 * NOUT];
    const int tid = threadIdx.x;
    if (tid < NOUT) sBN[tid] = g_scale[tid];
    else            sBN[128 + (tid - 128)] = g_shift[tid - 128];
    __syncthreads();

    long long i = (long long)blockIdx.x * 256 + tid;   // NE*16 = 12.8M exact
    int e = (int)(i >> 4), q = (int)(i & 15);

    int dst;
    if (g_idx64) dst = (int)reinterpret_cast<const long long*>(eidx)[2ll * e + 1];
    else         dst = reinterpret_cast<const int*>(eidx)[2 * e + 1];

    const float* row = g_pre + (size_t)e * NOUT;
    float4 xc4 = *reinterpret_cast<const float4*>(row + q * 4);
    float4 xf4 = *reinterpret_cast<const float4*>(row + 64 + q * 4);
    float xc[4] = {xc4.x, xc4.y, xc4.z, xc4.w};
    float xf[4] = {xf4.x, xf4.y, xf4.z, xf4.w};

    float m[4];
#pragma unroll
    for (int u = 0; u < 4; u++) {
        int c = q * 4 + u;
        float vc = xc[u] * sBN[c]      + sBN[NOUT + c];
        float vf = xf[u] * sBN[64 + c] + sBN[NOUT + 64 + c];
        float sp = fmaxf(vc, 0.f) + log1pf(__expf(-fabsf(vc)));   // softplus
        float sg = __fdividef(1.f, 1.f + __expf(-vf));            // sigmoid
        m[u] = sp * sg;
    }
    float* ptr = out + (long long)dst * ND + q * 4;
    asm volatile("red.global.add.v4.f32 [%0], {%1,%2,%3,%4};"
                 :: "l"(ptr), "f"(m[0]), "f"(m[1]), "f"(m[2]), "f"(m[3])
                 : "memory");
}

// ---------------------------------------------------------------------------
extern "C" void kernel_launch(void* const* d_in, const int* in_sizes, int n_in,
                              void* d_out, int out_size) {
    const float* atom  = (const float*)d_in[0];
    const float* edgef = (const float*)d_in[1];
    const float* Wf    = (const float*)d_in[2];
    const float* gf    = (const float*)d_in[4];
    const float* bf    = (const float*)d_in[5];
    const float* Wc    = (const float*)d_in[6];
    const float* gc    = (const float*)d_in[8];
    const float* bc    = (const float*)d_in[9];
    const void*  eidx  = d_in[10];
    float* out = (float*)d_out;

    cudaFuncSetAttribute(pass0_kernel,
                         cudaFuncAttributeMaxDynamicSharedMemorySize,
                         SMEM0_BYTES);

    prep_kernel<<<2048, 256>>>(atom, Wf, Wc, (const int*)eidx, out);
    pass0_kernel<<<NE / ET, THREADS0, SMEM0_BYTES>>>(atom, edgef, eidx);
    finalize_kernel<<<1, 128>>>(gc, bc, gf, bf);
    pass1_kernel<<<(NE * 16) / 256, 256>>>(eidx, out);
}

// round 6
// speedup vs baseline: 2.0377x; 1.1812x over previous
#include <cuda_runtime.h>
#include <cuda_bf16.h>
#include <mma.h>
#include <math.h>

using namespace nvcuda;

#define NA 50000
#define NE 800000
#define ND 64
#define FULL 192
#define NOUT 128          // combined: cols 0..63 = core, 64..127 = filter
#define ET 64             // edges per tile
#define NTILES (NE / ET)  // 12500
#define GRID0 148
#define THREADS0 256
#define WLD 132           // W smem leading dim (pad: 132 mod 32 = 4)
#define ZLD 196           // z smem leading dim (196 mod 32 = 4)
#define BN_EPS 1e-5f

// dyn smem: W (192x132) + 2 z-tiles (64x196) + 2x(src,dst) idx
#define SMEM0_BYTES ((FULL * WLD + 2 * ET * ZLD) * 4 + 4 * ET * 4)

__device__ __align__(16) float g_Wt[FULL * NOUT];   // Wt[k][o], tf32-rounded
__device__ float g_sum[NOUT];
__device__ float g_sumsq[NOUT];
__device__ float g_scale[NOUT];
__device__ float g_shift[NOUT];
__device__ int   g_idx64;
__device__ float g_pre[(size_t)NE * NOUT];          // 409.6 MB scratch

__device__ __forceinline__ void cp_async16(void* sdst, const void* gsrc) {
    unsigned saddr = (unsigned)__cvta_generic_to_shared(sdst);
    asm volatile("cp.async.ca.shared.global [%0], [%1], 16;"
                 :: "r"(saddr), "l"(gsrc) : "memory");
}

// ---------------------------------------------------------------------------
__global__ void prep_kernel(const float* __restrict__ atom,
                            const float* __restrict__ Wf,
                            const float* __restrict__ Wc,
                            const int* __restrict__ eidx_i32,
                            float* __restrict__ out) {
    int tid = blockIdx.x * blockDim.x + threadIdx.x;
    int stride = gridDim.x * blockDim.x;
    for (int i = tid; i < NA * ND; i += stride) out[i] = atom[i];
    for (int i = tid; i < FULL * NOUT; i += stride) {
        int k = i / NOUT, o = i % NOUT;
        float w = (o < ND) ? Wc[o * FULL + k] : Wf[(o - ND) * FULL + k];
        g_Wt[i] = wmma::__float_to_tf32(w);
    }
    if (tid < NOUT) { g_sum[tid] = 0.f; g_sumsq[tid] = 0.f; }
    if (tid == 0) {
        int any = 0;
        for (int k = 0; k < 512; k++) any |= eidx_i32[2 * k + 1];
        g_idx64 = (any == 0) ? 1 : 0;   // int64 => zero high words
    }
}

// ---------------------------------------------------------------------------
__global__ void finalize_kernel(const float* __restrict__ gc,
                                const float* __restrict__ bc,
                                const float* __restrict__ gf,
                                const float* __restrict__ bf) {
    int c = threadIdx.x;
    if (c < NOUT) {
        float mean = g_sum[c] * (1.f / (float)NE);
        float var  = g_sumsq[c] * (1.f / (float)NE) - mean * mean;
        float inv  = rsqrtf(var + BN_EPS);
        float gamma = (c < ND) ? gc[c] : gf[c - ND];
        float beta  = (c < ND) ? bc[c] : bf[c - ND];
        g_scale[c] = inv * gamma;
        g_shift[c] = beta - mean * inv * gamma;
    }
}

// ---------------------------------------------------------------------------
// PASS 0: persistent tf32 GEMM. 148 blocks x 256 threads. W in smem (once),
// double-buffered cp.async z-tiles, 64 edges/tile, warp = 32 edges x 32 cols.
// Streams pre-activations to g_pre; column stats in regs -> atomics at end.
// ---------------------------------------------------------------------------
__global__ __launch_bounds__(THREADS0, 1)
void pass0_kernel(const float* __restrict__ atom,
                  const float* __restrict__ edgef,
                  const void*  __restrict__ eidx) {
    extern __shared__ __align__(16) float smem[];
    float* sW  = smem;                      // 192*132
    float* zb[2];
    zb[0] = smem + FULL * WLD;              // 64*196
    zb[1] = zb[0] + ET * ZLD;
    int* sSrc = (int*)(zb[1] + ET * ZLD);   // [2][64]
    int* sDst = sSrc + 2 * ET;

    const int tid = threadIdx.x;
    const int bid = blockIdx.x;
    const int nt  = (NTILES - bid + GRID0 - 1) / GRID0;   // tiles: bid + s*148
    const bool i64 = (g_idx64 != 0);

    // ---- W: global -> smem (once), repack ldm 128 -> 132 ----
    for (int i = tid; i < FULL * 32; i += THREADS0) {
        int k = i >> 5, c = (i & 31) * 4;
        cp_async16(sW + k * WLD + c, g_Wt + k * NOUT + c);
    }

    auto stageIdx = [&](int s, int slot) {
        if (tid < ET && s < nt) {
            long long e = ((long long)bid + (long long)s * GRID0) * ET + tid;
            if (i64) {
                const long long* p = reinterpret_cast<const long long*>(eidx);
                sSrc[slot * ET + tid] = (int)p[2 * e];
                sDst[slot * ET + tid] = (int)p[2 * e + 1];
            } else {
                const int* p = reinterpret_cast<const int*>(eidx);
                sSrc[slot * ET + tid] = p[2 * e];
                sDst[slot * ET + tid] = p[2 * e + 1];
            }
        }
    };
    auto gather = [&](int s, int slot) {
        if (s < nt) {
            long long e0 = ((long long)bid + (long long)s * GRID0) * ET;
            float* zbuf = zb[slot];
            for (int i = tid; i < ET * 48; i += THREADS0) {
                int e = i / 48, seg = i % 48;
                int col = seg * 4;
                const float* g;
                if (seg < 16)      g = atom  + (long long)sDst[slot * ET + e] * ND + col;
                else if (seg < 32) g = atom  + (long long)sSrc[slot * ET + e] * ND + (col - 64);
                else               g = edgef + (e0 + e) * ND + (col - 128);
                cp_async16(zbuf + e * ZLD + col, g);
            }
        }
        asm volatile("cp.async.commit_group;" ::: "memory");
    };

    // ---- prologue ----
    stageIdx(0, 0);
    __syncthreads();
    gather(0, 0);          // commits group with W copy
    stageIdx(1, 1);
    __syncthreads();

    // warp tile: m0 = (w&1)*32 edges, n0 = (w>>1)*32 cols
    const int w  = tid >> 5;
    const int m0 = (w & 1) * 32;
    const int n0 = (w >> 1) * 32;

    const int scol = tid & 127;        // stats column for this thread
    const int sgrp = tid >> 7;         // edge half (0/1)
    float s_acc = 0.f, q_acc = 0.f;

    wmma::fragment<wmma::matrix_a, 16, 16, 8, wmma::precision::tf32, wmma::row_major> a0, a1;
    wmma::fragment<wmma::matrix_b, 16, 16, 8, wmma::precision::tf32, wmma::row_major> b0, b1;
    wmma::fragment<wmma::accumulator, 16, 16, 8, float> acc[2][2];

    for (int s = 0; s < nt; s++) {
        const int slot = s & 1;
        const float* zcur = zb[slot];
        long long e0 = ((long long)bid + (long long)s * GRID0) * ET;

        asm volatile("cp.async.wait_group 0;" ::: "memory");
        __syncthreads();                 // gather(s) visible; zb[slot^1] free

        gather(s + 1, slot ^ 1);         // overlaps with MMA below

#pragma unroll
        for (int m = 0; m < 2; m++)
#pragma unroll
            for (int n = 0; n < 2; n++) wmma::fill_fragment(acc[m][n], 0.f);

#pragma unroll
        for (int k = 0; k < FULL / 8; k++) {
            wmma::load_matrix_sync(a0, zcur + (m0)      * ZLD + k * 8, ZLD);
            wmma::load_matrix_sync(a1, zcur + (m0 + 16) * ZLD + k * 8, ZLD);
            wmma::load_matrix_sync(b0, sW + (k * 8) * WLD + n0, WLD);
            wmma::load_matrix_sync(b1, sW + (k * 8) * WLD + n0 + 16, WLD);
            wmma::mma_sync(acc[0][0], a0, b0, acc[0][0]);
            wmma::mma_sync(acc[0][1], a0, b1, acc[0][1]);
            wmma::mma_sync(acc[1][0], a1, b0, acc[1][0]);
            wmma::mma_sync(acc[1][1], a1, b1, acc[1][1]);
        }

#pragma unroll
        for (int m = 0; m < 2; m++)
#pragma unroll
            for (int n = 0; n < 2; n++)
                wmma::store_matrix_sync(
                    g_pre + (size_t)(e0 + m0 + m * 16) * NOUT + n0 + n * 16,
                    acc[m][n], NOUT, wmma::mem_row_major);
        __syncthreads();                 // C visible for stats

        // column stats: thread owns (scol, 32 edges), L2-resident rows
        const float* base = g_pre + (size_t)(e0 + sgrp * 32) * NOUT + scol;
#pragma unroll
        for (int e = 0; e < 32; e++) {
            float v = base[(size_t)e * NOUT];
            s_acc += v; q_acc += v * v;
        }

        stageIdx(s + 2, slot);           // idx for tile s+2 into freed slot
    }

    atomicAdd(&g_sum[scol],   s_acc);
    atomicAdd(&g_sumsq[scol], q_acc);
}

// ---------------------------------------------------------------------------
// PASS 1: streaming epilogue: BN fold + softplus*sigmoid + red.v4 scatter.
// ---------------------------------------------------------------------------
__global__ __launch_bounds__(256)
void pass1_kernel(const void* __restrict__ eidx,
                  float* __restrict__ out) {
    __shared__ float sBN[2 * NOUT];
    const int tid = threadIdx.x;
    if (tid < NOUT) sBN[tid] = g_scale[tid];
    else            sBN[128 + (tid - 128)] = g_shift[tid - 128];
    __syncthreads();

    long long i = (long long)blockIdx.x * 256 + tid;   // NE*16 total
    int e = (int)(i >> 4), q = (int)(i & 15);

    int dst;
    if (g_idx64) dst = (int)reinterpret_cast<const long long*>(eidx)[2ll * e + 1];
    else         dst = reinterpret_cast<const int*>(eidx)[2 * e + 1];

    const float* row = g_pre + (size_t)e * NOUT;
    float4 xc4 = *reinterpret_cast<const float4*>(row + q * 4);
    float4 xf4 = *reinterpret_cast<const float4*>(row + 64 + q * 4);
    float xc[4] = {xc4.x, xc4.y, xc4.z, xc4.w};
    float xf[4] = {xf4.x, xf4.y, xf4.z, xf4.w};

    float m[4];
#pragma unroll
    for (int u = 0; u < 4; u++) {
        int c = q * 4 + u;
        float vc = xc[u] * sBN[c]      + sBN[NOUT + c];
        float vf = xf[u] * sBN[64 + c] + sBN[NOUT + 64 + c];
        float sp = fmaxf(vc, 0.f) + log1pf(__expf(-fabsf(vc)));   // softplus
        float sg = __fdividef(1.f, 1.f + __expf(-vf));            // sigmoid
        m[u] = sp * sg;
    }
    float* ptr = out + (long long)dst * ND + q * 4;
    asm volatile("red.global.add.v4.f32 [%0], {%1,%2,%3,%4};"
                 :: "l"(ptr), "f"(m[0]), "f"(m[1]), "f"(m[2]), "f"(m[3])
                 : "memory");
}

// ---------------------------------------------------------------------------
extern "C" void kernel_launch(void* const* d_in, const int* in_sizes, int n_in,
                              void* d_out, int out_size) {
    const float* atom  = (const float*)d_in[0];
    const float* edgef = (const float*)d_in[1];
    const float* Wf    = (const float*)d_in[2];
    const float* gf    = (const float*)d_in[4];
    const float* bf    = (const float*)d_in[5];
    const float* Wc    = (const float*)d_in[6];
    const float* gc    = (const float*)d_in[8];
    const float* bc    = (const float*)d_in[9];
    const void*  eidx  = d_in[10];
    float* out = (float*)d_out;

    cudaFuncSetAttribute(pass0_kernel,
                         cudaFuncAttributeMaxDynamicSharedMemorySize,
                         SMEM0_BYTES);

    prep_kernel<<<2048, 256>>>(atom, Wf, Wc, (const int*)eidx, out);
    pass0_kernel<<<GRID0, THREADS0, SMEM0_BYTES>>>(atom, edgef, eidx);
    finalize_kernel<<<1, 128>>>(gc, bc, gf, bf);
    pass1_kernel<<<(NE * 16) / 256, 256>>>(eidx, out);
}

// round 7
// speedup vs baseline: 2.2525x; 1.1054x over previous
#include <cuda_runtime.h>
#include <cuda_bf16.h>
#include <mma.h>
#include <math.h>

using namespace nvcuda;

#define NA 50000
#define NE 800000
#define ND 64
#define FULL 192
#define NOUT 128          // combined: cols 0..63 = core, 64..127 = filter
#define ET 128            // edges per tile
#define NTILES (NE / ET)  // 6250
#define GRID0 148
#define THREADS0 512
#define WLD 132           // W smem leading dim (mod 32 = 4)
#define ZLD 68            // z chunk leading dim: 64 cols + pad (mod 32 = 4)
#define BN_EPS 1e-5f

// dyn smem: W (192x132) + 2 z-chunks (128x68) + 2x(src,dst)[128]
#define SMEM0_BYTES ((FULL * WLD + 2 * ET * ZLD) * 4 + 4 * ET * 4)

__device__ __align__(16) float g_Wt[FULL * NOUT];   // Wt[k][o], tf32-rounded
__device__ float g_sum[NOUT];
__device__ float g_sumsq[NOUT];
__device__ float g_scale[NOUT];
__device__ float g_shift[NOUT];
__device__ int   g_idx64;
__device__ float g_pre[(size_t)NE * NOUT];          // 409.6 MB scratch

__device__ __forceinline__ void cp_async16(void* sdst, const void* gsrc) {
    unsigned saddr = (unsigned)__cvta_generic_to_shared(sdst);
    asm volatile("cp.async.ca.shared.global [%0], [%1], 16;"
                 :: "r"(saddr), "l"(gsrc) : "memory");
}

// ---------------------------------------------------------------------------
__global__ void prep_kernel(const float* __restrict__ atom,
                            const float* __restrict__ Wf,
                            const float* __restrict__ Wc,
                            const int* __restrict__ eidx_i32,
                            float* __restrict__ out) {
    int tid = blockIdx.x * blockDim.x + threadIdx.x;
    int stride = gridDim.x * blockDim.x;
    for (int i = tid; i < NA * ND; i += stride) out[i] = atom[i];
    for (int i = tid; i < FULL * NOUT; i += stride) {
        int k = i / NOUT, o = i % NOUT;
        float w = (o < ND) ? Wc[o * FULL + k] : Wf[(o - ND) * FULL + k];
        g_Wt[i] = wmma::__float_to_tf32(w);
    }
    if (tid < NOUT) { g_sum[tid] = 0.f; g_sumsq[tid] = 0.f; }
    if (tid == 0) {
        int any = 0;
        for (int k = 0; k < 512; k++) any |= eidx_i32[2 * k + 1];
        g_idx64 = (any == 0) ? 1 : 0;   // int64 => zero high words
    }
}

// ---------------------------------------------------------------------------
__global__ void finalize_kernel(const float* __restrict__ gc,
                                const float* __restrict__ bc,
                                const float* __restrict__ gf,
                                const float* __restrict__ bf) {
    int c = threadIdx.x;
    if (c < NOUT) {
        float mean = g_sum[c] * (1.f / (float)NE);
        float var  = g_sumsq[c] * (1.f / (float)NE) - mean * mean;
        float inv  = rsqrtf(var + BN_EPS);
        float gamma = (c < ND) ? gc[c] : gf[c - ND];
        float beta  = (c < ND) ? bc[c] : bf[c - ND];
        g_scale[c] = inv * gamma;
        g_shift[c] = beta - mean * inv * gamma;
    }
}

// ---------------------------------------------------------------------------
// PASS 0: persistent tf32 GEMM, 148 x 512 threads. W resident in smem.
// 128-edge tiles, K split into 3 chunks of 64 (dst/src/edge); chunks are the
// cp.async pipeline unit (double-buffered, wait_group 1 keeps one in flight).
// Warp grid 4m x 4n (32 edges x 32 cols per warp).
// ---------------------------------------------------------------------------
__global__ __launch_bounds__(THREADS0, 1)
void pass0_kernel(const float* __restrict__ atom,
                  const float* __restrict__ edgef,
                  const void*  __restrict__ eidx) {
    extern __shared__ __align__(16) float smem[];
    float* sW = smem;                       // 192*132
    float* zb[2];
    zb[0] = smem + FULL * WLD;              // 128*68 each
    zb[1] = zb[0] + ET * ZLD;
    int* sSrc = (int*)(zb[1] + ET * ZLD);   // [2][128]
    int* sDst = sSrc + 2 * ET;

    const int tid = threadIdx.x;
    const int bid = blockIdx.x;
    const int nt  = (NTILES - bid + GRID0 - 1) / GRID0;   // tiles bid + t*148
    const bool i64 = (g_idx64 != 0);

    auto stageIdx = [&](int t) {
        if (tid < ET && t < nt) {
            int slot = t & 1;
            long long e = ((long long)bid + (long long)t * GRID0) * ET + tid;
            if (i64) {
                const long long* p = reinterpret_cast<const long long*>(eidx);
                sSrc[slot * ET + tid] = (int)p[2 * e];
                sDst[slot * ET + tid] = (int)p[2 * e + 1];
            } else {
                const int* p = reinterpret_cast<const int*>(eidx);
                sSrc[slot * ET + tid] = p[2 * e];
                sDst[slot * ET + tid] = p[2 * e + 1];
            }
        }
    };
    // gather K-chunk c (tile t = c/3, phase p = c%3) into zb[c&1]; always commits
    auto gather = [&](int c) {
        int t = c / 3, p = c - 3 * t;
        if (t < nt) {
            int islot = t & 1;
            long long e0 = ((long long)bid + (long long)t * GRID0) * ET;
            float* zbuf = zb[c & 1];
            for (int i = tid; i < ET * 16; i += THREADS0) {
                int e = i >> 4, q = i & 15;
                int col = q * 4;
                const float* g;
                if (p == 0)      g = atom  + (long long)sDst[islot * ET + e] * ND + col;
                else if (p == 1) g = atom  + (long long)sSrc[islot * ET + e] * ND + col;
                else             g = edgef + (e0 + e) * ND + col;
                cp_async16(zbuf + e * ZLD + col, g);
            }
        }
        asm volatile("cp.async.commit_group;" ::: "memory");
    };

    // ---- prologue: W copy + chunk0 (group 0), chunk1 (group 1) ----
    stageIdx(0);
    __syncthreads();
    for (int i = tid; i < FULL * 32; i += THREADS0) {
        int k = i >> 5, c4 = (i & 31) * 4;
        cp_async16(sW + k * WLD + c4, g_Wt + k * NOUT + c4);
    }
    gather(0);          // W + chunk0 committed together
    gather(1);

    const int w  = tid >> 5;
    const int m0 = (w & 3) * 32;
    const int n0 = (w >> 2) * 32;
    const int scol = tid & 127;        // stats column
    const int sgrp = tid >> 7;         // edge quarter (0..3)
    float s_acc = 0.f, q_acc = 0.f;

    wmma::fragment<wmma::matrix_a, 16, 16, 8, wmma::precision::tf32, wmma::row_major> a0, a1;
    wmma::fragment<wmma::matrix_b, 16, 16, 8, wmma::precision::tf32, wmma::row_major> b0, b1;
    wmma::fragment<wmma::accumulator, 16, 16, 8, float> acc[2][2];

    for (int t = 0; t < nt; t++) {
        long long e0 = ((long long)bid + (long long)t * GRID0) * ET;

#pragma unroll
        for (int p = 0; p < 3; p++) {
            const int c = 3 * t + p;
            asm volatile("cp.async.wait_group 1;" ::: "memory");
            __syncthreads();             // chunk c visible; zb[c&1] owned

            if (p == 0) {
                stageIdx(t + 1);         // idx for next tile (used at c+3)
#pragma unroll
                for (int m = 0; m < 2; m++)
#pragma unroll
                    for (int n = 0; n < 2; n++) wmma::fill_fragment(acc[m][n], 0.f);
            }

            const float* z = zb[c & 1];
#pragma unroll
            for (int k = 0; k < 8; k++) {
                wmma::load_matrix_sync(a0, z + (m0)      * ZLD + k * 8, ZLD);
                wmma::load_matrix_sync(a1, z + (m0 + 16) * ZLD + k * 8, ZLD);
                wmma::load_matrix_sync(b0, sW + (p * 64 + k * 8) * WLD + n0,      WLD);
                wmma::load_matrix_sync(b1, sW + (p * 64 + k * 8) * WLD + n0 + 16, WLD);
                wmma::mma_sync(acc[0][0], a0, b0, acc[0][0]);
                wmma::mma_sync(acc[0][1], a0, b1, acc[0][1]);
                wmma::mma_sync(acc[1][0], a1, b0, acc[1][0]);
                wmma::mma_sync(acc[1][1], a1, b1, acc[1][1]);
            }
            __syncthreads();             // all warps done with zb[c&1]
            gather(c + 2);               // refill freed buffer (in flight)
        }

        // ---- tile epilogue: stream C to g_pre, fold stats from L2 ----
#pragma unroll
        for (int m = 0; m < 2; m++)
#pragma unroll
            for (int n = 0; n < 2; n++)
                wmma::store_matrix_sync(
                    g_pre + (size_t)(e0 + m0 + m * 16) * NOUT + n0 + n * 16,
                    acc[m][n], NOUT, wmma::mem_row_major);
        __syncthreads();                 // C visible block-wide

        const float* base = g_pre + (size_t)(e0 + sgrp * 32) * NOUT + scol;
#pragma unroll
        for (int e = 0; e < 32; e++) {
            float v = base[(size_t)e * NOUT];
            s_acc += v; q_acc += v * v;
        }
    }

    atomicAdd(&g_sum[scol],   s_acc);
    atomicAdd(&g_sumsq[scol], q_acc);
}

// ---------------------------------------------------------------------------
// PASS 1: streaming epilogue: BN fold + softplus*sigmoid + red.v4 scatter.
// ---------------------------------------------------------------------------
__global__ __launch_bounds__(256)
void pass1_kernel(const void* __restrict__ eidx,
                  float* __restrict__ out) {
    __shared__ float sBN[2 * NOUT];
    const int tid = threadIdx.x;
    if (tid < NOUT) sBN[tid] = g_scale[tid];
    else            sBN[128 + (tid - 128)] = g_shift[tid - 128];
    __syncthreads();

    long long i = (long long)blockIdx.x * 256 + tid;   // NE*16 total
    int e = (int)(i >> 4), q = (int)(i & 15);

    int dst;
    if (g_idx64) dst = (int)reinterpret_cast<const long long*>(eidx)[2ll * e + 1];
    else         dst = reinterpret_cast<const int*>(eidx)[2 * e + 1];

    const float* row = g_pre + (size_t)e * NOUT;
    float4 xc4 = *reinterpret_cast<const float4*>(row + q * 4);
    float4 xf4 = *reinterpret_cast<const float4*>(row + 64 + q * 4);
    float xc[4] = {xc4.x, xc4.y, xc4.z, xc4.w};
    float xf[4] = {xf4.x, xf4.y, xf4.z, xf4.w};

    float m[4];
#pragma unroll
    for (int u = 0; u < 4; u++) {
        int c = q * 4 + u;
        float vc = xc[u] * sBN[c]      + sBN[NOUT + c];
        float vf = xf[u] * sBN[64 + c] + sBN[NOUT + 64 + c];
        float sp = fmaxf(vc, 0.f) + log1pf(__expf(-fabsf(vc)));   // softplus
        float sg = __fdividef(1.f, 1.f + __expf(-vf));            // sigmoid
        m[u] = sp * sg;
    }
    float* ptr = out + (long long)dst * ND + q * 4;
    asm volatile("red.global.add.v4.f32 [%0], {%1,%2,%3,%4};"
                 :: "l"(ptr), "f"(m[0]), "f"(m[1]), "f"(m[2]), "f"(m[3])
                 : "memory");
}

// ---------------------------------------------------------------------------
extern "C" void kernel_launch(void* const* d_in, const int* in_sizes, int n_in,
                              void* d_out, int out_size) {
    const float* atom  = (const float*)d_in[0];
    const float* edgef = (const float*)d_in[1];
    const float* Wf    = (const float*)d_in[2];
    const float* gf    = (const float*)d_in[4];
    const float* bf    = (const float*)d_in[5];
    const float* Wc    = (const float*)d_in[6];
    const float* gc    = (const float*)d_in[8];
    const float* bc    = (const float*)d_in[9];
    const void*  eidx  = d_in[10];
    float* out = (float*)d_out;

    cudaFuncSetAttribute(pass0_kernel,
                         cudaFuncAttributeMaxDynamicSharedMemorySize,
                         SMEM0_BYTES);

    prep_kernel<<<2048, 256>>>(atom, Wf, Wc, (const int*)eidx, out);
    pass0_kernel<<<GRID0, THREADS0, SMEM0_BYTES>>>(atom, edgef, eidx);
    finalize_kernel<<<1, 128>>>(gc, bc, gf, bf);
    pass1_kernel<<<(NE * 16) / 256, 256>>>(eidx, out);
}

// round 9
// speedup vs baseline: 4.5930x; 2.0391x over previous
#include <cuda_runtime.h>
#include <cuda_fp16.h>
#include <mma.h>
#include <math.h>
#include <stdint.h>

using namespace nvcuda;

#define NA 50000
#define NE 800000
#define ND 64
#define FULL 192
#define NOUT 128          // cols 0..63 = core, 64..127 = filter
#define ET 128            // edges per tile
#define NTILES (NE / ET)  // 6250
#define GRID0 148
#define THREADS0 512
#define WLDH 136          // W smem leading dim in halves (272B; 68 words, mod32=4)
#define ZLDH 72           // z chunk leading dim in halves (144B; 36 words, mod32=4)
#define BN_EPS 1e-5f

// dyn smem: W (192x136 half) + 2 z-chunks (128x72 half) + 2x(src,dst)[128]
#define SMEM0_BYTES ((FULL * WLDH + 2 * ET * ZLDH) * 2 + 4 * ET * 4)

__device__ __align__(16) __half g_Wt_h[FULL * NOUT];   // Wt[k][o] half
__device__ __align__(16) __half g_atom_h[NA * ND];     // atom features, half
__device__ __align__(16) __half g_edge_h[(size_t)NE * ND]; // edge features, half
__device__ float g_sum[NOUT];
__device__ float g_sumsq[NOUT];
__device__ float g_scale[NOUT];
__device__ float g_shift[NOUT];
__device__ int   g_idx64;
__device__ float g_pre[(size_t)NE * NOUT];             // 409.6 MB scratch

__device__ __forceinline__ void cp_async16(void* sdst, const void* gsrc) {
    unsigned saddr = (unsigned)__cvta_generic_to_shared(sdst);
    asm volatile("cp.async.ca.shared.global [%0], [%1], 16;"
                 :: "r"(saddr), "l"(gsrc) : "memory");
}

// ---------------------------------------------------------------------------
// prep: out = atom copy; atom/edge/W -> half; zero stats; idx dtype sniff
// ---------------------------------------------------------------------------
__global__ void prep_kernel(const float* __restrict__ atom,
                            const float* __restrict__ edgef,
                            const float* __restrict__ Wf,
                            const float* __restrict__ Wc,
                            const int* __restrict__ eidx_i32,
                            float* __restrict__ out) {
    int tid = blockIdx.x * blockDim.x + threadIdx.x;
    int stride = gridDim.x * blockDim.x;

    // atom: copy f32 -> out, convert -> half
    for (int i = tid; i < (NA * ND) / 4; i += stride) {
        float4 v = reinterpret_cast<const float4*>(atom)[i];
        reinterpret_cast<float4*>(out)[i] = v;
        __half2* h = reinterpret_cast<__half2*>(g_atom_h) + 2 * i;
        h[0] = __floats2half2_rn(v.x, v.y);
        h[1] = __floats2half2_rn(v.z, v.w);
    }
    // edge features -> half
    for (long long i = tid; i < ((long long)NE * ND) / 4; i += stride) {
        float4 v = reinterpret_cast<const float4*>(edgef)[i];
        __half2* h = reinterpret_cast<__half2*>(g_edge_h) + 2 * i;
        h[0] = __floats2half2_rn(v.x, v.y);
        h[1] = __floats2half2_rn(v.z, v.w);
    }
    // W transposed -> half (bias cancels inside batchnorm)
    for (int i = tid; i < FULL * NOUT; i += stride) {
        int k = i / NOUT, o = i % NOUT;
        float w = (o < ND) ? Wc[o * FULL + k] : Wf[(o - ND) * FULL + k];
        g_Wt_h[i] = __float2half_rn(w);
    }
    if (tid < NOUT) { g_sum[tid] = 0.f; g_sumsq[tid] = 0.f; }
    if (tid == 0) {
        int any = 0;
        for (int k = 0; k < 512; k++) any |= eidx_i32[2 * k + 1];
        g_idx64 = (any == 0) ? 1 : 0;   // int64 => zero high words
    }
}

// ---------------------------------------------------------------------------
__global__ void finalize_kernel(const float* __restrict__ gc,
                                const float* __restrict__ bc,
                                const float* __restrict__ gf,
                                const float* __restrict__ bf) {
    int c = threadIdx.x;
    if (c < NOUT) {
        float mean = g_sum[c] * (1.f / (float)NE);
        float var  = g_sumsq[c] * (1.f / (float)NE) - mean * mean;
        float inv  = rsqrtf(var + BN_EPS);
        float gamma = (c < ND) ? gc[c] : gf[c - ND];
        float beta  = (c < ND) ? bc[c] : bf[c - ND];
        g_scale[c] = inv * gamma;
        g_shift[c] = beta - mean * inv * gamma;
    }
}

// ---------------------------------------------------------------------------
// PASS 0: persistent fp16 GEMM, 148 x 512 threads. W resident in smem (half).
// 128-edge tiles, K in 3 chunks of 64 halves (dst/src/edge), double-buffered
// cp.async (wait_group 1). Warp grid 4m x 4n (32 edges x 32 cols per warp).
// Streams pre-activations to g_pre; column stats in regs -> atomics at end.
// ---------------------------------------------------------------------------
__global__ __launch_bounds__(THREADS0, 1)
void pass0_kernel(const void* __restrict__ eidx) {
    extern __shared__ __align__(16) unsigned char smraw[];
    __half* sW = reinterpret_cast<__half*>(smraw);        // 192*136 halves
    __half* zb[2];
    zb[0] = sW + FULL * WLDH;                             // 128*72 halves each
    zb[1] = zb[0] + ET * ZLDH;
    int* sSrc = reinterpret_cast<int*>(zb[1] + ET * ZLDH);   // [2][ET]
    int* sDst = sSrc + 2 * ET;

    const int tid = threadIdx.x;
    const int bid = blockIdx.x;
    const int nt  = (NTILES - bid + GRID0 - 1) / GRID0;   // tiles bid + t*148
    const bool i64 = (g_idx64 != 0);

    auto stageIdx = [&](int t) {
        if (tid < ET && t < nt) {
            int slot = t & 1;
            long long e = ((long long)bid + (long long)t * GRID0) * ET + tid;
            if (i64) {
                const long long* p = reinterpret_cast<const long long*>(eidx);
                sSrc[slot * ET + tid] = (int)p[2 * e];
                sDst[slot * ET + tid] = (int)p[2 * e + 1];
            } else {
                const int* p = reinterpret_cast<const int*>(eidx);
                sSrc[slot * ET + tid] = p[2 * e];
                sDst[slot * ET + tid] = p[2 * e + 1];
            }
        }
    };
    // gather K-chunk c (tile t = c/3, phase p = c%3) into zb[c&1]; always commits
    auto gather = [&](int c) {
        int t = c / 3, p = c - 3 * t;
        if (t < nt) {
            int islot = t & 1;
            long long e0 = ((long long)bid + (long long)t * GRID0) * ET;
            __half* zbuf = zb[c & 1];
            // 8 x 16B (= 64 halves) per edge row
            for (int i = tid; i < ET * 8; i += THREADS0) {
                int e = i >> 3, q = i & 7;
                const __half* g;
                if (p == 0)      g = g_atom_h + (long long)sDst[islot*ET + e] * ND + q * 8;
                else if (p == 1) g = g_atom_h + (long long)sSrc[islot*ET + e] * ND + q * 8;
                else             g = g_edge_h + (e0 + e) * ND + q * 8;
                cp_async16(zbuf + e * ZLDH + q * 8, g);
            }
        }
        asm volatile("cp.async.commit_group;" ::: "memory");
    };

    // ---- prologue: W copy + chunk0 (group 0), chunk1 (group 1) ----
    stageIdx(0);
    __syncthreads();
    for (int i = tid; i < (FULL * WLDH) / 8; i += THREADS0) {
        // copy row-wise: 136 halves/row = 17 x 16B
        int k = i / 17, q = i % 17;
        if (q < 16)
            cp_async16(sW + k * WLDH + q * 8, g_Wt_h + k * NOUT + q * 8);
    }
    gather(0);          // W + chunk0 committed together
    gather(1);

    const int w  = tid >> 5;
    const int m0 = (w & 3) * 32;
    const int n0 = (w >> 2) * 32;
    const int scol = tid & 127;        // stats column
    const int sgrp = tid >> 7;         // edge quarter (0..3)
    float s_acc = 0.f, q_acc = 0.f;

    wmma::fragment<wmma::matrix_a, 16, 16, 16, __half, wmma::row_major> a0, a1;
    wmma::fragment<wmma::matrix_b, 16, 16, 16, __half, wmma::row_major> b0, b1;
    wmma::fragment<wmma::accumulator, 16, 16, 16, float> acc[2][2];

    for (int t = 0; t < nt; t++) {
        long long e0 = ((long long)bid + (long long)t * GRID0) * ET;

#pragma unroll
        for (int p = 0; p < 3; p++) {
            const int c = 3 * t + p;
            asm volatile("cp.async.wait_group 1;" ::: "memory");
            __syncthreads();             // chunk c visible; zb[c&1] owned

            if (p == 0) {
                stageIdx(t + 1);         // idx for next tile (used at c+3)
#pragma unroll
                for (int m = 0; m < 2; m++)
#pragma unroll
                    for (int n = 0; n < 2; n++) wmma::fill_fragment(acc[m][n], 0.f);
            }

            const __half* z = zb[c & 1];
#pragma unroll
            for (int k = 0; k < 4; k++) {
                wmma::load_matrix_sync(a0, z + (m0)      * ZLDH + k * 16, ZLDH);
                wmma::load_matrix_sync(a1, z + (m0 + 16) * ZLDH + k * 16, ZLDH);
                wmma::load_matrix_sync(b0, sW + (p * 64 + k * 16) * WLDH + n0,      WLDH);
                wmma::load_matrix_sync(b1, sW + (p * 64 + k * 16) * WLDH + n0 + 16, WLDH);
                wmma::mma_sync(acc[0][0], a0, b0, acc[0][0]);
                wmma::mma_sync(acc[0][1], a0, b1, acc[0][1]);
                wmma::mma_sync(acc[1][0], a1, b0, acc[1][0]);
                wmma::mma_sync(acc[1][1], a1, b1, acc[1][1]);
            }
            __syncthreads();             // all warps done with zb[c&1]
            gather(c + 2);               // refill freed buffer (in flight)
        }

        // ---- tile epilogue: stream C to g_pre, fold stats from L2 ----
#pragma unroll
        for (int m = 0; m < 2; m++)
#pragma unroll
            for (int n = 0; n < 2; n++)
                wmma::store_matrix_sync(
                    g_pre + (size_t)(e0 + m0 + m * 16) * NOUT + n0 + n * 16,
                    acc[m][n], NOUT, wmma::mem_row_major);
        __syncthreads();                 // C visible block-wide

        const float* base = g_pre + (size_t)(e0 + sgrp * 32) * NOUT + scol;
#pragma unroll
        for (int e = 0; e < 32; e++) {
            float v = base[(size_t)e * NOUT];
            s_acc += v; q_acc += v * v;
        }
    }

    atomicAdd(&g_sum[scol],   s_acc);
    atomicAdd(&g_sumsq[scol], q_acc);
}

// ---------------------------------------------------------------------------
// PASS 1: streaming epilogue: BN fold + softplus*sigmoid + red.v4 scatter.
// ---------------------------------------------------------------------------
__global__ __launch_bounds__(256)
void pass1_kernel(const void* __restrict__ eidx,
                  float* __restrict__ out) {
    __shared__ float sBN[2 * NOUT];
    const int tid = threadIdx.x;
    if (tid < NOUT) sBN[tid] = g_scale[tid];
    else            sBN[128 + (tid - 128)] = g_shift[tid - 128];
    __syncthreads();

    long long i = (long long)blockIdx.x * 256 + tid;   // NE*16 total
    int e = (int)(i >> 4), q = (int)(i & 15);

    int dst;
    if (g_idx64) dst = (int)reinterpret_cast<const long long*>(eidx)[2ll * e + 1];
    else         dst = reinterpret_cast<const int*>(eidx)[2 * e + 1];

    const float* row = g_pre + (size_t)e * NOUT;
    float4 xc4 = *reinterpret_cast<const float4*>(row + q * 4);
    float4 xf4 = *reinterpret_cast<const float4*>(row + 64 + q * 4);
    float xc[4] = {xc4.x, xc4.y, xc4.z, xc4.w};
    float xf[4] = {xf4.x, xf4.y, xf4.z, xf4.w};

    float m[4];
#pragma unroll
    for (int u = 0; u < 4; u++) {
        int c = q * 4 + u;
        float vc = xc[u] * sBN[c]      + sBN[NOUT + c];
        float vf = xf[u] * sBN[64 + c] + sBN[NOUT + 64 + c];
        float sp = fmaxf(vc, 0.f) + log1pf(__expf(-fabsf(vc)));   // softplus
        float sg = __fdividef(1.f, 1.f + __expf(-vf));            // sigmoid
        m[u] = sp * sg;
    }
    float* ptr = out + (long long)dst * ND + q * 4;
    asm volatile("red.global.add.v4.f32 [%0], {%1,%2,%3,%4};"
                 :: "l"(ptr), "f"(m[0]), "f"(m[1]), "f"(m[2]), "f"(m[3])
                 : "memory");
}

// ---------------------------------------------------------------------------
extern "C" void kernel_launch(void* const* d_in, const int* in_sizes, int n_in,
                              void* d_out, int out_size) {
    const float* atom  = (const float*)d_in[0];
    const float* edgef = (const float*)d_in[1];
    const float* Wf    = (const float*)d_in[2];
    const float* gf    = (const float*)d_in[4];
    const float* bf    = (const float*)d_in[5];
    const float* Wc    = (const float*)d_in[6];
    const float* gc    = (const float*)d_in[8];
    const float* bc    = (const float*)d_in[9];
    const void*  eidx  = d_in[10];
    float* out = (float*)d_out;

    cudaFuncSetAttribute(pass0_kernel,
                         cudaFuncAttributeMaxDynamicSharedMemorySize,
                         SMEM0_BYTES);

    prep_kernel<<<2048, 256>>>(atom, edgef, Wf, Wc, (const int*)eidx, out);
    pass0_kernel<<<GRID0, THREADS0, SMEM0_BYTES>>>(eidx);
    finalize_kernel<<<1, 128>>>(gc, bc, gf, bf);
    pass1_kernel<<<(NE * 16) / 256, 256>>>(eidx, out);
}